// round 1
// baseline (speedup 1.0000x reference)
#include <cuda_runtime.h>
#include <cuda_bf16.h>
#include <cstdint>
#include <math.h>

// ---------------- problem constants ----------------
#define BB 16
#define SS 1024
#define DD 1024
#define HH 8
#define QKD 128          // q/k width
#define EXPD 2048
#define NROWS (BB*SS)    // 16384
#define EOUT (2*QKD + 2*EXPD)  // 4352

// ---------------- scratch (static device, no allocation) ----------------
__device__ __nv_bfloat16 g_xn[(size_t)NROWS * DD];
__device__ __nv_bfloat16 g_proj[(size_t)NROWS * EOUT];
__device__ __nv_bfloat16 g_concat[(size_t)NROWS * EXPD];   // [0,1024): geglu_local, [1024,2048): attention
__device__ __nv_bfloat16 g_v[(size_t)NROWS * DD];
__device__ __nv_bfloat16 g_wexp[(size_t)EOUT * DD];
__device__ __nv_bfloat16 g_wproj[(size_t)DD * EXPD];

// ---------------- helpers ----------------
__device__ __forceinline__ void mma16816(float d[4], const uint32_t a[4], const uint32_t b[2]) {
    asm volatile(
        "mma.sync.aligned.m16n8k16.row.col.f32.bf16.bf16.f32 "
        "{%0,%1,%2,%3},{%4,%5,%6,%7},{%8,%9},{%0,%1,%2,%3};\n"
        : "+f"(d[0]), "+f"(d[1]), "+f"(d[2]), "+f"(d[3])
        : "r"(a[0]), "r"(a[1]), "r"(a[2]), "r"(a[3]), "r"(b[0]), "r"(b[1]));
}

__device__ __forceinline__ uint32_t packbf(float a, float b) {
    __nv_bfloat162 t = __floats2bfloat162_rn(a, b);
    return *reinterpret_cast<uint32_t*>(&t);
}

// ---------------- fp32 -> bf16 weight convert ----------------
__global__ void cvt_kernel(const float* __restrict__ src, __nv_bfloat16* __restrict__ dst, int n4) {
    int i = blockIdx.x * blockDim.x + threadIdx.x;
    if (i < n4) {
        float4 v = ((const float4*)src)[i];
        __nv_bfloat162* d = (__nv_bfloat162*)(dst + (size_t)i * 4);
        d[0] = __floats2bfloat162_rn(v.x, v.y);
        d[1] = __floats2bfloat162_rn(v.z, v.w);
    }
}

// ---------------- LayerNorm: one block (256 thr) per row ----------------
__global__ __launch_bounds__(256) void ln_kernel(const float* __restrict__ x,
                                                 const float* __restrict__ w,
                                                 __nv_bfloat16* __restrict__ out) {
    int row = blockIdx.x;
    float4 v = ((const float4*)(x + (size_t)row * DD))[threadIdx.x];
    float s = v.x + v.y + v.z + v.w;
    float s2 = v.x * v.x + v.y * v.y + v.z * v.z + v.w * v.w;
#pragma unroll
    for (int o = 16; o; o >>= 1) {
        s += __shfl_xor_sync(0xffffffffu, s, o);
        s2 += __shfl_xor_sync(0xffffffffu, s2, o);
    }
    __shared__ float rs[8], rs2[8];
    int warp = threadIdx.x >> 5, lane = threadIdx.x & 31;
    if (!lane) { rs[warp] = s; rs2[warp] = s2; }
    __syncthreads();
    if (threadIdx.x == 0) {
        float a = 0.f, b = 0.f;
#pragma unroll
        for (int i = 0; i < 8; i++) { a += rs[i]; b += rs2[i]; }
        rs[0] = a; rs2[0] = b;
    }
    __syncthreads();
    float mu = rs[0] * (1.f / DD);
    float var = rs2[0] * (1.f / DD) - mu * mu;
    float r = rsqrtf(var + 1e-5f);
    float4 w4 = ((const float4*)w)[threadIdx.x];
    __nv_bfloat16* op = out + (size_t)row * DD + threadIdx.x * 4;
    *(__nv_bfloat162*)op = __floats2bfloat162_rn((v.x - mu) * r * w4.x, (v.y - mu) * r * w4.y);
    *(__nv_bfloat162*)(op + 2) = __floats2bfloat162_rn((v.z - mu) * r * w4.z, (v.w - mu) * r * w4.w);
}

// ---------------- bf16 GEMM: C[M,N] = A[M,K] * Bw[N,K]^T ----------------
// BM=128, BN=128, BK=32, 256 threads, warps 2x4, warp tile 64x32 (4x4 m16n8k16)
#define GBM 128
#define GBN 128
#define GBK 32
#define GLDT 40

__device__ __forceinline__ void st_tile(__nv_bfloat16* s, int lr, int lc, uint4 r0, uint4 r1) {
    *(uint2*)&s[lr * GLDT + lc] = make_uint2(r0.x, r0.y);
    *(uint2*)&s[lr * GLDT + lc + 4] = make_uint2(r0.z, r0.w);
    *(uint2*)&s[(lr + 64) * GLDT + lc] = make_uint2(r1.x, r1.y);
    *(uint2*)&s[(lr + 64) * GLDT + lc + 4] = make_uint2(r1.z, r1.w);
}

template <int NCOLS, bool RESID>
__global__ __launch_bounds__(256) void gemm_bf16(const __nv_bfloat16* __restrict__ A,
                                                 const __nv_bfloat16* __restrict__ Bw,
                                                 __nv_bfloat16* __restrict__ Cb,
                                                 const float* __restrict__ resid,
                                                 float* __restrict__ Cf,
                                                 int K) {
    __shared__ __nv_bfloat16 As[2][GBM * GLDT];
    __shared__ __nv_bfloat16 Bs[2][GBN * GLDT];
    const int tid = threadIdx.x;
    const int warp = tid >> 5, lane = tid & 31;
    const int gid = lane >> 2, tig = lane & 3;
    const int wm = (warp >> 2) * 64, wn = (warp & 3) * 32;
    const int bm = blockIdx.y, bn = blockIdx.x;
    const int lr = tid >> 2;
    const int lc = (tid & 3) * 8;
    const __nv_bfloat16* Ag = A + ((size_t)(bm * GBM + lr)) * K + lc;
    const __nv_bfloat16* Bg = Bw + ((size_t)(bn * GBN + lr)) * K + lc;
    const size_t rstride = (size_t)64 * K;

    float acc[4][4][4];
#pragma unroll
    for (int i = 0; i < 4; i++)
#pragma unroll
        for (int j = 0; j < 4; j++)
#pragma unroll
            for (int r = 0; r < 4; r++) acc[i][j][r] = 0.f;

    uint4 ra0 = *(const uint4*)Ag;
    uint4 ra1 = *(const uint4*)(Ag + rstride);
    uint4 rb0 = *(const uint4*)Bg;
    uint4 rb1 = *(const uint4*)(Bg + rstride);
    st_tile(As[0], lr, lc, ra0, ra1);
    st_tile(Bs[0], lr, lc, rb0, rb1);
    __syncthreads();

    const int KT = K / GBK;
    for (int kt = 0; kt < KT; kt++) {
        int cur = kt & 1;
        if (kt + 1 < KT) {
            const __nv_bfloat16* ap = Ag + (kt + 1) * GBK;
            const __nv_bfloat16* bp = Bg + (kt + 1) * GBK;
            ra0 = *(const uint4*)ap;
            ra1 = *(const uint4*)(ap + rstride);
            rb0 = *(const uint4*)bp;
            rb1 = *(const uint4*)(bp + rstride);
        }
#pragma unroll
        for (int ks = 0; ks < 2; ks++) {
            uint32_t af[4][4], bfr[4][2];
#pragma unroll
            for (int mi = 0; mi < 4; mi++) {
                const __nv_bfloat16* p = &As[cur][(wm + mi * 16 + gid) * GLDT + ks * 16 + tig * 2];
                af[mi][0] = *(const uint32_t*)p;
                af[mi][1] = *(const uint32_t*)(p + 8 * GLDT);
                af[mi][2] = *(const uint32_t*)(p + 8);
                af[mi][3] = *(const uint32_t*)(p + 8 * GLDT + 8);
            }
#pragma unroll
            for (int ni = 0; ni < 4; ni++) {
                const __nv_bfloat16* p = &Bs[cur][(wn + ni * 8 + gid) * GLDT + ks * 16 + tig * 2];
                bfr[ni][0] = *(const uint32_t*)p;
                bfr[ni][1] = *(const uint32_t*)(p + 8);
            }
#pragma unroll
            for (int mi = 0; mi < 4; mi++)
#pragma unroll
                for (int ni = 0; ni < 4; ni++) mma16816(acc[mi][ni], af[mi], bfr[ni]);
        }
        if (kt + 1 < KT) {
            st_tile(As[cur ^ 1], lr, lc, ra0, ra1);
            st_tile(Bs[cur ^ 1], lr, lc, rb0, rb1);
        }
        __syncthreads();
    }

#pragma unroll
    for (int mi = 0; mi < 4; mi++) {
        int r0 = bm * GBM + wm + mi * 16 + gid;
#pragma unroll
        for (int ni = 0; ni < 4; ni++) {
            int col = bn * GBN + wn + ni * 8 + tig * 2;
            size_t i0 = (size_t)r0 * NCOLS + col;
            size_t i1 = (size_t)(r0 + 8) * NCOLS + col;
            if (!RESID) {
                *(__nv_bfloat162*)&Cb[i0] = __floats2bfloat162_rn(acc[mi][ni][0], acc[mi][ni][1]);
                *(__nv_bfloat162*)&Cb[i1] = __floats2bfloat162_rn(acc[mi][ni][2], acc[mi][ni][3]);
            } else {
                float2 v0 = make_float2(acc[mi][ni][0] + resid[i0], acc[mi][ni][1] + resid[i0 + 1]);
                float2 v1 = make_float2(acc[mi][ni][2] + resid[i1], acc[mi][ni][3] + resid[i1 + 1]);
                *(float2*)&Cf[i0] = v0;
                *(float2*)&Cf[i1] = v1;
            }
        }
    }
}

// ---------------- GeGLU ----------------
__global__ __launch_bounds__(256) void geglu_kernel(const __nv_bfloat16* __restrict__ proj,
                                                    __nv_bfloat16* __restrict__ concat,
                                                    __nv_bfloat16* __restrict__ vbuf) {
    int i = blockIdx.x * blockDim.x + threadIdx.x;  // over NROWS * (EXPD/2)
    int row = i >> 10;
    int col = (i & 1023) * 2;
    const size_t pb = (size_t)row * EOUT;
    __nv_bfloat162 l2 = *(const __nv_bfloat162*)&proj[pb + 2 * QKD + col];
    __nv_bfloat162 p2 = *(const __nv_bfloat162*)&proj[pb + 2 * QKD + EXPD + col];
    float p0 = __bfloat162float(p2.x), p1 = __bfloat162float(p2.y);
    float g0 = __bfloat162float(l2.x) * 0.5f * p0 * (1.f + erff(p0 * 0.70710678118654752f));
    float g1 = __bfloat162float(l2.y) * 0.5f * p1 * (1.f + erff(p1 * 0.70710678118654752f));
    __nv_bfloat162 o = __floats2bfloat162_rn(g0, g1);
    if (col < 1024)
        *(__nv_bfloat162*)&concat[(size_t)row * EXPD + col] = o;
    else
        *(__nv_bfloat162*)&vbuf[(size_t)row * DD + col - 1024] = o;
}

// ---------------- flash attention (mma, online softmax) ----------------
// grid (8 q-chunks, B*H); block 256 (8 warps x 16 q rows)
__global__ __launch_bounds__(256, 1) void attn_kernel(const __nv_bfloat16* __restrict__ proj,
                                                      const __nv_bfloat16* __restrict__ vbuf,
                                                      __nv_bfloat16* __restrict__ concat,
                                                      const float* __restrict__ pbm_p,
                                                      const int* __restrict__ fi_p,
                                                      const int* __restrict__ li_p) {
    __shared__ __nv_bfloat16 Ks[128][20];
    __shared__ __nv_bfloat16 Vt[128][136];
    const int tid = threadIdx.x, warp = tid >> 5, lane = tid & 31;
    const int gid = lane >> 2, tig = lane & 3;
    const int bh = blockIdx.y, b = bh >> 3, h = bh & 7;
    const int qbase = blockIdx.x * 128;
    float pbm = *pbm_p;
    const float sp = fmaxf(pbm, 0.f) + log1pf(expf(-fabsf(pbm)));
    int fi = *fi_p; if (fi >= SS) fi = 0;
    int li = *li_p; if (li >= SS) li = 0;

    const int i0 = qbase + warp * 16 + gid;
    const int i1 = i0 + 8;
    uint32_t qa[4];
    {
        const size_t base = ((size_t)(b * SS + i0)) * EOUT + h * 16 + tig * 2;
        qa[0] = *(const uint32_t*)&proj[base];
        qa[1] = *(const uint32_t*)&proj[base + (size_t)8 * EOUT];
        qa[2] = *(const uint32_t*)&proj[base + 8];
        qa[3] = *(const uint32_t*)&proj[base + (size_t)8 * EOUT + 8];
    }
    float m0 = -1e30f, m1 = -1e30f, l0 = 0.f, l1 = 0.f;
    float o[16][4];
#pragma unroll
    for (int ni = 0; ni < 16; ni++)
#pragma unroll
        for (int r = 0; r < 4; r++) o[ni][r] = 0.f;

    const float scale = 0.25f;  // 1/sqrt(16)
    const int qmax = qbase + 127;

    for (int kc = 0; kc < SS / 128; kc++) {
        const int kmin = kc * 128;
        if (kmin > qmax && !((qmax >= fi) && (kmin + 127 >= li))) continue;  // uniform per block

        {  // K chunk -> smem [key][16]
            int r = tid >> 1, c = (tid & 1) * 8;
            const uint4 kv = *(const uint4*)&proj[((size_t)(b * SS + kmin + r)) * EOUT + QKD + h * 16 + c];
            *(uint2*)&Ks[r][c] = make_uint2(kv.x, kv.y);
            *(uint2*)&Ks[r][c + 4] = make_uint2(kv.z, kv.w);
        }
        {  // V chunk transposed -> smem [dv][key]
            int d2 = (tid & 63) * 2, r0 = tid >> 6;
            const size_t gb = ((size_t)(b * SS + kmin)) * DD + h * 128 + d2;
#pragma unroll
            for (int j = 0; j < 32; j++) {
                int r = r0 + j * 4;
                __nv_bfloat162 vv = *(const __nv_bfloat162*)&vbuf[gb + (size_t)r * DD];
                Vt[d2][r] = vv.x;
                Vt[d2 + 1][r] = vv.y;
            }
        }
        __syncthreads();

        float sc[16][4];
#pragma unroll
        for (int ni = 0; ni < 16; ni++) {
            sc[ni][0] = sc[ni][1] = sc[ni][2] = sc[ni][3] = 0.f;
            uint32_t bfr[2];
            bfr[0] = *(const uint32_t*)&Ks[ni * 8 + gid][tig * 2];
            bfr[1] = *(const uint32_t*)&Ks[ni * 8 + gid][tig * 2 + 8];
            mma16816(sc[ni], qa, bfr);
        }
        float rmax0 = -1e30f, rmax1 = -1e30f;
#pragma unroll
        for (int ni = 0; ni < 16; ni++) {
            int jc = kmin + ni * 8 + tig * 2;
#pragma unroll
            for (int r = 0; r < 4; r++) {
                int j = jc + (r & 1);
                int i = (r < 2) ? i0 : i1;
                bool ok = (j <= i) || ((i >= fi) && (j >= li));
                float s = ok ? fmaf(sc[ni][r], scale, sp * (float)(j - i)) : -1e30f;
                sc[ni][r] = s;
                if (r < 2) rmax0 = fmaxf(rmax0, s);
                else rmax1 = fmaxf(rmax1, s);
            }
        }
        rmax0 = fmaxf(rmax0, __shfl_xor_sync(0xffffffffu, rmax0, 1));
        rmax0 = fmaxf(rmax0, __shfl_xor_sync(0xffffffffu, rmax0, 2));
        rmax1 = fmaxf(rmax1, __shfl_xor_sync(0xffffffffu, rmax1, 1));
        rmax1 = fmaxf(rmax1, __shfl_xor_sync(0xffffffffu, rmax1, 2));
        float mn0 = fmaxf(m0, rmax0), mn1 = fmaxf(m1, rmax1);
        float cor0 = __expf(m0 - mn0), cor1 = __expf(m1 - mn1);
        m0 = mn0; m1 = mn1;
        float rs0 = 0.f, rs1 = 0.f;
#pragma unroll
        for (int ni = 0; ni < 16; ni++) {
            sc[ni][0] = __expf(sc[ni][0] - m0); rs0 += sc[ni][0];
            sc[ni][1] = __expf(sc[ni][1] - m0); rs0 += sc[ni][1];
            sc[ni][2] = __expf(sc[ni][2] - m1); rs1 += sc[ni][2];
            sc[ni][3] = __expf(sc[ni][3] - m1); rs1 += sc[ni][3];
        }
        rs0 += __shfl_xor_sync(0xffffffffu, rs0, 1);
        rs0 += __shfl_xor_sync(0xffffffffu, rs0, 2);
        rs1 += __shfl_xor_sync(0xffffffffu, rs1, 1);
        rs1 += __shfl_xor_sync(0xffffffffu, rs1, 2);
        l0 = l0 * cor0 + rs0;
        l1 = l1 * cor1 + rs1;
#pragma unroll
        for (int ni = 0; ni < 16; ni++) {
            o[ni][0] *= cor0; o[ni][1] *= cor0; o[ni][2] *= cor1; o[ni][3] *= cor1;
        }
#pragma unroll
        for (int ks = 0; ks < 8; ks++) {
            uint32_t pa[4];
            pa[0] = packbf(sc[2 * ks][0], sc[2 * ks][1]);
            pa[1] = packbf(sc[2 * ks][2], sc[2 * ks][3]);
            pa[2] = packbf(sc[2 * ks + 1][0], sc[2 * ks + 1][1]);
            pa[3] = packbf(sc[2 * ks + 1][2], sc[2 * ks + 1][3]);
#pragma unroll
            for (int ni = 0; ni < 16; ni++) {
                uint32_t vb[2];
                const __nv_bfloat16* p = &Vt[ni * 8 + gid][ks * 16 + tig * 2];
                vb[0] = *(const uint32_t*)p;
                vb[1] = *(const uint32_t*)(p + 8);
                mma16816(o[ni], pa, vb);
            }
        }
        __syncthreads();
    }

    float inv0 = 1.f / l0, inv1 = 1.f / l1;
#pragma unroll
    for (int ni = 0; ni < 16; ni++) {
        int col = 1024 + h * 128 + ni * 8 + tig * 2;
        *(__nv_bfloat162*)&concat[((size_t)(b * SS) + i0) * EXPD + col] =
            __floats2bfloat162_rn(o[ni][0] * inv0, o[ni][1] * inv0);
        *(__nv_bfloat162*)&concat[((size_t)(b * SS) + i1) * EXPD + col] =
            __floats2bfloat162_rn(o[ni][2] * inv1, o[ni][3] * inv1);
    }
}

// ---------------- launch ----------------
extern "C" void kernel_launch(void* const* d_in, const int* in_sizes, int n_in,
                              void* d_out, int out_size) {
    const float* x = (const float*)d_in[0];
    const float* norm_w = (const float*)d_in[1];
    const float* expand_w = (const float*)d_in[2];
    const float* project_w = (const float*)d_in[3];
    const float* pbm = (const float*)d_in[4];
    const int* fi = (const int*)d_in[5];
    const int* li = (const int*)d_in[6];
    float* out = (float*)d_out;

    void *p_xn, *p_proj, *p_concat, *p_v, *p_wexp, *p_wproj;
    cudaGetSymbolAddress(&p_xn, g_xn);
    cudaGetSymbolAddress(&p_proj, g_proj);
    cudaGetSymbolAddress(&p_concat, g_concat);
    cudaGetSymbolAddress(&p_v, g_v);
    cudaGetSymbolAddress(&p_wexp, g_wexp);
    cudaGetSymbolAddress(&p_wproj, g_wproj);
    __nv_bfloat16* xn = (__nv_bfloat16*)p_xn;
    __nv_bfloat16* proj = (__nv_bfloat16*)p_proj;
    __nv_bfloat16* concat = (__nv_bfloat16*)p_concat;
    __nv_bfloat16* vb = (__nv_bfloat16*)p_v;
    __nv_bfloat16* wexp = (__nv_bfloat16*)p_wexp;
    __nv_bfloat16* wproj = (__nv_bfloat16*)p_wproj;

    // weights -> bf16
    cvt_kernel<<<(EOUT * DD / 4 + 255) / 256, 256>>>(expand_w, wexp, EOUT * DD / 4);
    cvt_kernel<<<(DD * EXPD / 4 + 255) / 256, 256>>>(project_w, wproj, DD * EXPD / 4);

    // layernorm
    ln_kernel<<<NROWS, 256>>>(x, norm_w, xn);

    // expand GEMM: proj[16384,4352] = xn[16384,1024] @ wexp[4352,1024]^T
    gemm_bf16<EOUT, false><<<dim3(EOUT / GBN, NROWS / GBM), 256>>>(xn, wexp, proj, nullptr, nullptr, DD);

    // geglu -> concat[:, :1024] and v buffer
    geglu_kernel<<<NROWS * (EXPD / 2) / 256, 256>>>(proj, concat, vb);

    // attention -> concat[:, 1024:2048]
    attn_kernel<<<dim3(SS / 128, BB * HH), 256>>>(proj, vb, concat, pbm, fi, li);

    // project GEMM + residual: out[16384,1024] = concat[16384,2048] @ wproj[1024,2048]^T + x
    gemm_bf16<DD, true><<<dim3(DD / GBN, NROWS / GBM), 256>>>(concat, wproj, nullptr, x, out, EXPD);
}